// round 8
// baseline (speedup 1.0000x reference)
#include <cuda_runtime.h>

#define ROWS 1024
#define COLS 1024
#define NN (ROWS * COLS)

#define RHOGW 9810.0f            // RHO_W * GRAV
#define INV_SEC_PER_A (1.0f / 31556926.0f)
#define FLOW_COEFF 0.0405f

#define TS 32                    // output tile
#define KF 8                     // fused iterations per launch
#define RW (TS + 2*KF)           // 48
#define RN (RW * RW)             // 2304
#define SPAD RW                  // sq guard pad (one row each side)

// Scratch (device globals: no allocations allowed)
__device__ float4 g_w4[NN];      // incoming weights: {left, right, up, down}
__device__ float  g_runoff[NN];
__device__ float  g_q[2][NN];

// ---------------- fused prep: phi -> gs -> w4 + runoff, one pass ----------------
#define PT 32
#define PH2 36
#define PH1 34

__global__ __launch_bounds__(256) void k_prep(const float* __restrict__ melt,
                                              const float* __restrict__ bed,
                                              const float* __restrict__ wp,
                                              const float* __restrict__ area,
                                              const int*  __restrict__ status) {
    __shared__ float sphi[PH2 * PH2];
    __shared__ float sgs[PH1 * PH1];
    const int ox = blockIdx.x * PT, oy = blockIdx.y * PT;

    for (int idx = threadIdx.x; idx < PH2 * PH2; idx += 256) {
        int iy = idx / PH2, ix = idx % PH2;
        int gy = oy + iy - 2, gx = ox + ix - 2;
        float p = __int_as_float(0x7f800000);     // +INF sentinel: contributes 0 drop
        if (gx >= 0 && gx < COLS && gy >= 0 && gy < ROWS) {
            int g = gy * COLS + gx;
            p = fmaf(RHOGW, bed[g], wp[g]);
        }
        sphi[idx] = p;
    }
    __syncthreads();

    for (int idx = threadIdx.x; idx < PH1 * PH1; idx += 256) {
        int iy = idx / PH1, ix = idx % PH1;
        int gy = oy + iy - 1, gx = ox + ix - 1;
        float gs = 0.0f;
        if (gx >= 0 && gx < COLS && gy >= 0 && gy < ROWS) {
            int g = gy * COLS + gx;
            if (status[g] == 0) {
                int c = (iy + 1) * PH2 + (ix + 1);
                float p = sphi[c];
                float s = 0.0f;
                s += fmaxf(p - sphi[c - 1], 0.0f);
                s += fmaxf(p - sphi[c + 1], 0.0f);
                s += fmaxf(p - sphi[c - PH2], 0.0f);
                s += fmaxf(p - sphi[c + PH2], 0.0f);
                gs = (s > 0.0f) ? (1.0f / s) : 1.0f;
            }
        }
        sgs[idx] = gs;
    }
    __syncthreads();

    for (int idx = threadIdx.x; idx < PT * PT; idx += 256) {
        int iy = idx / PT, ix = idx % PT;
        int gy = oy + iy, gx = ox + ix;
        int g = gy * COLS + gx;
        int cp = (iy + 2) * PH2 + (ix + 2);
        int cg = (iy + 1) * PH1 + (ix + 1);
        float p = sphi[cp];
        float4 w = make_float4(0.0f, 0.0f, 0.0f, 0.0f);
        if (gx > 0)        w.x = fmaxf(sphi[cp - 1]   - p, 0.0f) * sgs[cg - 1];
        if (gx < COLS - 1) w.y = fmaxf(sphi[cp + 1]   - p, 0.0f) * sgs[cg + 1];
        if (gy > 0)        w.z = fmaxf(sphi[cp - PH2] - p, 0.0f) * sgs[cg - PH1];
        if (gy < ROWS - 1) w.w = fmaxf(sphi[cp + PH2] - p, 0.0f) * sgs[cg + PH1];
        g_w4[g] = w;
        g_runoff[g] = melt[g] * area[g] * INV_SEC_PER_A;
    }
}

// ---------------- fused Jacobi: 8 iters, coalesced-staged loads ----------------
// 256 threads (16x16), each owns a 3x3 patch of a 48x48 region (32x32 tile,
// halo 8). All global reads staged coalesced through smem, then picked up
// per-patch with conflict-free LDS. The same smem is re-aliased as the q
// ping-pong for the iteration loop (R2 ring-exchange scheme).
template <bool INIT, bool FINAL>
__global__ __launch_bounds__(256, 3)
void k_fused(int qsel,
             const float* __restrict__ conduit,
             float* __restrict__ out) {
    __shared__ __align__(16) float smem[4 * RN];   // 36.9 KB, multi-purpose

    const int tid = threadIdx.x;
    const int tx = tid & 15, ty = tid >> 4;
    const int px = tx * 3, py = ty * 3;
    const int ox = blockIdx.x * TS - KF;
    const int oy = blockIdx.y * TS - KF;

    const float* __restrict__ qsrc = g_q[qsel];
    float*       __restrict__ qdst = g_q[qsel ^ 1];

    // ---- stage 1: w4, coalesced global -> smem -> per-patch registers ----
    float4* stage4 = (float4*)smem;
#pragma unroll
    for (int k = 0; k < 9; k++) {
        const int idx = tid + k * 256;              // 0..2303
        const int iy = idx / RW, ix = idx - iy * RW;
        const int gy = oy + iy, gx = ox + ix;
        float4 v = make_float4(0.0f, 0.0f, 0.0f, 0.0f);
        if (gx >= 0 && gx < COLS && gy >= 0 && gy < ROWS)
            v = g_w4[gy * COLS + gx];
        stage4[idx] = v;
    }
    __syncthreads();
    float4 w[3][3];
#pragma unroll
    for (int r = 0; r < 3; r++)
#pragma unroll
        for (int c = 0; c < 3; c++)
            w[r][c] = stage4[(py + r) * RW + px + c];
    __syncthreads();

    // ---- stage 2: runoff (+ qsrc), coalesced -> smem -> registers ----
    float* sro = smem;
    float* sqs = smem + RN;
#pragma unroll
    for (int k = 0; k < 9; k++) {
        const int idx = tid + k * 256;
        const int iy = idx / RW, ix = idx - iy * RW;
        const int gy = oy + iy, gx = ox + ix;
        float rv = 0.0f, qv = 0.0f;
        if (gx >= 0 && gx < COLS && gy >= 0 && gy < ROWS) {
            const int g = gy * COLS + gx;
            rv = g_runoff[g];
            if (!INIT) qv = qsrc[g];
        }
        sro[idx] = rv;
        if (!INIT) sqs[idx] = qv;
    }
    __syncthreads();
    float ro[3][3], q[3][3];
#pragma unroll
    for (int r = 0; r < 3; r++)
#pragma unroll
        for (int c = 0; c < 3; c++) {
            const int idx = (py + r) * RW + px + c;
            ro[r][c] = sro[idx];
            q[r][c]  = INIT ? ro[r][c] : sqs[idx];
        }
    __syncthreads();

    // ---- stage 3: re-alias smem as q ping-pong, seed, iterate ----
    float* sq0 = smem;                         // RN + 2*SPAD = 2400 floats
    float* sq1 = smem + (RN + 2 * SPAD);       // 2400 floats (total 4800 <= 9216)
    if (tid < SPAD) {
        sq0[tid] = 0.0f;
        sq1[tid] = 0.0f;
        sq0[SPAD + RN + tid] = 0.0f;
        sq1[SPAD + RN + tid] = 0.0f;
    }
    const int base = SPAD + py * RW + px;
#pragma unroll
    for (int r = 0; r < 3; r++)
#pragma unroll
        for (int c = 0; c < 3; c++)
            if (!(r == 1 && c == 1)) sq0[base + r * RW + c] = q[r][c];
    __syncthreads();

#pragma unroll
    for (int it = 0; it < KF; it++) {
        const float* __restrict__ qs = (it & 1) ? sq1 : sq0;
        float*       __restrict__ qd = (it & 1) ? sq0 : sq1;

        // 12-ring from neighboring threads (previous iteration values)
        float t0 = qs[base - RW],     t1 = qs[base - RW + 1],     t2 = qs[base - RW + 2];
        float b0 = qs[base + 3 * RW], b1 = qs[base + 3 * RW + 1], b2 = qs[base + 3 * RW + 2];
        float l0 = qs[base - 1],      l1 = qs[base + RW - 1],     l2 = qs[base + 2 * RW - 1];
        float r0 = qs[base + 3],      r1 = qs[base + RW + 3],     r2 = qs[base + 2 * RW + 3];

        float n[3][3];
#pragma unroll
        for (int r = 0; r < 3; r++) {
#pragma unroll
            for (int c = 0; c < 3; c++) {
                const float lf = (c == 0) ? ((r == 0) ? l0 : (r == 1) ? l1 : l2) : q[r][c - 1];
                const float rt = (c == 2) ? ((r == 0) ? r0 : (r == 1) ? r1 : r2) : q[r][c + 1];
                const float up = (r == 0) ? ((c == 0) ? t0 : (c == 1) ? t1 : t2) : q[r - 1][c];
                const float dn = (r == 2) ? ((c == 0) ? b0 : (c == 1) ? b1 : b2) : q[r + 1][c];
                float acc = ro[r][c];
                acc = fmaf(w[r][c].x, lf, acc);
                acc = fmaf(w[r][c].y, rt, acc);
                acc = fmaf(w[r][c].z, up, acc);
                acc = fmaf(w[r][c].w, dn, acc);
                n[r][c] = acc;
            }
        }
#pragma unroll
        for (int r = 0; r < 3; r++)
#pragma unroll
            for (int c = 0; c < 3; c++) q[r][c] = n[r][c];

        if (it != KF - 1) {
            // publish only the 8 border cells of the patch
            qd[base]              = q[0][0];
            qd[base + 1]          = q[0][1];
            qd[base + 2]          = q[0][2];
            qd[base + RW]         = q[1][0];
            qd[base + RW + 2]     = q[1][2];
            qd[base + 2 * RW]     = q[2][0];
            qd[base + 2 * RW + 1] = q[2][1];
            qd[base + 2 * RW + 2] = q[2][2];
            __syncthreads();
        }
    }

    // ---- write central 32x32 from registers ----
#pragma unroll
    for (int r = 0; r < 3; r++) {
#pragma unroll
        for (int c = 0; c < 3; c++) {
            const int ly = py + r, lx = px + c;
            if (lx >= KF && lx < KF + TS && ly >= KF && ly < KF + TS) {
                const int gy = oy + ly, gx = ox + lx;
                const int g = gy * COLS + gx;
                if (FINAL) {
                    const float cd = conduit[g];
                    const float c125 = cd * sqrtf(sqrtf(cd));   // conduit^1.25
                    const float t = q[r][c] * FLOW_COEFF * c125;
                    const bool core = (gx >= 1) & (gx <= COLS - 2) & (gy >= 1) & (gy <= ROWS - 2);
                    out[g] = core ? (t * t) : 0.0f;
                } else {
                    qdst[g] = q[r][c];
                }
            }
        }
    }
}

extern "C" void kernel_launch(void* const* d_in, const int* in_sizes, int n_in,
                              void* d_out, int out_size) {
    const float* melt    = (const float*)d_in[0];
    const float* bed     = (const float*)d_in[1];
    const float* wp      = (const float*)d_in[2];
    const float* area    = (const float*)d_in[3];
    const float* conduit = (const float*)d_in[4];
    const int*   status  = (const int*)d_in[5];
    float* out = (float*)d_out;

    dim3 pgrid(COLS / PT, ROWS / PT);
    k_prep<<<pgrid, 256>>>(melt, bed, wp, area, status);

    dim3 grid(COLS / TS, ROWS / TS);   // 32 x 32 tiles
    // 4 launches x 8 fused iterations = 32 iterations total
    k_fused<true,  false><<<grid, 256>>>(0, conduit, out);  // runoff -> g_q[1]
    k_fused<false, false><<<grid, 256>>>(1, conduit, out);  // g_q[1] -> g_q[0]
    k_fused<false, false><<<grid, 256>>>(0, conduit, out);  // g_q[0] -> g_q[1]
    k_fused<false, true ><<<grid, 256>>>(1, conduit, out);  // g_q[1] -> out
}